// round 3
// baseline (speedup 1.0000x reference)
#include <cuda_runtime.h>
#include <math.h>
#include <stdint.h>

#define B_ 16
#define C_ 80
#define N_ 22743          // 3*(361 + 1444 + 5776)
#define K_ 100
#define CELLS_ 7581
#define M_ (C_*K_)        // 8000
#define CAP_ 3072
#define TPB_ 512

// smem layout offsets for topk (bytes)
#define Q_BYTES   90976                 // N_*4 rounded to 16
#define CIDX_OFF  Q_BYTES               // CAP_ ints = 12288
#define BMP_OFF   (Q_BYTES + CAP_*4)    // 712 u32 = 2848
#define SMEM_TOPK (BMP_OFF + 2848)      // 106112

// ---------------- scratch (device globals; no allocations allowed) ----------
__device__ float g_boxes[B_*N_*4];
__device__ float g_conf_s[B_*N_];       // segment layout: noff + a*gg + cell
__device__ float g_lc_s[B_*N_];         // log(conf), same layout
__device__ float g_top_s[B_*M_];
__device__ float g_top_b[B_*M_*4];
__device__ float g_cand[B_*M_];

__constant__ int c_gg[3]   = {361, 1444, 5776};
__constant__ int c_noff[3] = {0, 1083, 5415};

__device__ __forceinline__ float sigmoidf_(float x) { return 1.0f/(1.0f+expf(-x)); }

// ---------------- stage 1: decode boxes + conf + lc -------------------------
__global__ void decode_kernel(const float* __restrict__ f0, const float* __restrict__ f1,
                              const float* __restrict__ f2, const float* __restrict__ anchors,
                              const float* __restrict__ imshape) {
    int tid = blockIdx.x * blockDim.x + threadIdx.x;
    if (tid >= B_*CELLS_) return;
    int b  = tid / CELLS_;
    int cp = tid % CELLS_;

    const float* feat; int g, l, noff, coff;
    if (cp < 361)        { feat = f0; g = 19; l = 0; noff = 0;    coff = 0;    }
    else if (cp < 1805)  { feat = f1; g = 38; l = 1; noff = 1083; coff = 361;  }
    else                 { feat = f2; g = 76; l = 2; noff = 5415; coff = 1805; }

    int cell = cp - coff;
    int gg = g * g;
    int gy = cell / g, gx = cell % g;

    float imh = imshape[0], imw = imshape[1];
    const float ih = 608.0f, iw = 608.0f;
    float r  = fminf(ih/imh, iw/imw);
    float nh = rintf(imh*r), nw = rintf(imw*r);
    float offy = (ih - nh) * 0.5f / ih, offx = (iw - nw) * 0.5f / iw;
    float scy  = ih / nh,               scx  = iw / nw;

    #pragma unroll
    for (int a = 0; a < 3; a++) {
        const float* base = feat + ((size_t)b*255 + a*85) * (size_t)gg + cell;
        float tx = base[0];
        float ty = base[(size_t)gg];
        float tw = base[2*(size_t)gg];
        float th = base[3*(size_t)gg];
        float to = base[4*(size_t)gg];
        float conf = sigmoidf_(to);
        float lc   = -log1pf(expf(-to));       // log(sigmoid(to)), stable

        float bx = (sigmoidf_(tx) + (float)gx) / (float)g;
        float by = (sigmoidf_(ty) + (float)gy) / (float)g;
        int aidx = (2 - l)*3 + a;
        float bw = expf(tw) * anchors[aidx*2 + 0] / ih;
        float bh = expf(th) * anchors[aidx*2 + 1] / iw;

        float y  = (by - offy) * scy;
        float x  = (bx - offx) * scx;
        float hh = bh * scy;
        float ww = bw * scx;

        int n = noff + cell*3 + a;
        float* ob = &g_boxes[((size_t)b*N_ + n)*4];
        ob[0] = (y - hh*0.5f) * imh;
        ob[1] = (x - ww*0.5f) * imw;
        ob[2] = (y + hh*0.5f) * imh;
        ob[3] = (x + ww*0.5f) * imw;

        int np = noff + a*gg + cell;           // segment layout
        g_conf_s[(size_t)b*N_ + np] = conf;
        g_lc_s[(size_t)b*N_ + np]   = lc;
    }
}

// ---------------- stage 2: per-(b,c) exact top-100 via q-screen -------------
__global__ __launch_bounds__(TPB_) void topk_kernel(const float* __restrict__ f0,
                                                    const float* __restrict__ f1,
                                                    const float* __restrict__ f2) {
    extern __shared__ char sm[];
    float* q = (float*)sm;                                        // N_ floats
    int*   cidx = (int*)(sm + CIDX_OFF);                          // CAP_ ints
    uint32_t* samp = (uint32_t*)(sm + CIDX_OFF);                  // overlay (512 u32)
    unsigned long long* su = (unsigned long long*)sm;             // overlay (CAP_ u64 <= Q_BYTES)
    uint32_t* bmp = (uint32_t*)(sm + BMP_OFF);                    // 712 u32 (fallback)

    __shared__ int wtot[16];
    __shared__ unsigned long long wmax[16];
    __shared__ int sh_cnt[3];
    __shared__ float sh_win;
    __shared__ int sh_ncand, sh_fb;

    int tid = threadIdx.x;
    int blk = blockIdx.x;
    int b = blk / C_, c = blk % C_;
    const float* feats[3] = {f0, f1, f2};

    // ---- phase 1: compute screen key q[n] = min(p,0) + lc  (no MUFU) ----
    for (int l = 0; l < 3; l++) {
        int gg = c_gg[l], noff = c_noff[l];
        for (int a = 0; a < 3; a++) {
            const float* pp  = feats[l] + ((size_t)(b*255 + a*85 + 5 + c)) * gg;
            const float* lcp = g_lc_s + (size_t)b*N_ + noff + a*gg;
            for (int i = tid; i < gg; i += TPB_)
                q[noff + i*3 + a] = fminf(pp[i], 0.0f) + lcp[i];
        }
    }
    __syncthreads();

    // ---- sample 512 keys, bitonic sort desc (mapped uint order) ----
    {
        float v = q[tid*44 + 17];
        uint32_t u = __float_as_uint(v);
        samp[tid] = (u & 0x80000000u) ? ~u : (u | 0x80000000u);
    }
    __syncthreads();
    for (int k = 2; k <= 512; k <<= 1)
        for (int j = k >> 1; j > 0; j >>= 1) {
            int ixj = tid ^ j;
            if (ixj > tid) {
                uint32_t A = samp[tid], Bv = samp[ixj];
                bool up = ((tid & k) == 0);
                if (up ? (A < Bv) : (A > Bv)) { samp[tid] = Bv; samp[ixj] = A; }
            }
            __syncthreads();
        }

    float tcand[3];
    {
        const int rr0 = 3, rr1 = 7, rr2 = 15;
        uint32_t us[3] = { samp[rr0], samp[rr1], samp[rr2] };
        #pragma unroll
        for (int t = 0; t < 3; t++) {
            uint32_t u = us[t];
            uint32_t bits = (u & 0x80000000u) ? (u & 0x7FFFFFFFu) : ~u;
            tcand[t] = __uint_as_float(bits);
        }
    }
    if (tid < 3) sh_cnt[tid] = 0;
    if (tid == 0) { sh_fb = 0; sh_ncand = 0; }
    __syncthreads();

    // ---- verify pass: count 3 thresholds (ballot-free, no hot atomics) ----
    {
        int c0 = 0, c1 = 0, c2 = 0;
        for (int i = tid; i < N_; i += TPB_) {
            float v = q[i];
            c0 += (v >= tcand[0]); c1 += (v >= tcand[1]); c2 += (v >= tcand[2]);
        }
        for (int d = 16; d; d >>= 1) {
            c0 += __shfl_down_sync(0xFFFFFFFFu, c0, d);
            c1 += __shfl_down_sync(0xFFFFFFFFu, c1, d);
            c2 += __shfl_down_sync(0xFFFFFFFFu, c2, d);
        }
        if ((tid & 31) == 0) {
            atomicAdd(&sh_cnt[0], c0); atomicAdd(&sh_cnt[1], c1); atomicAdd(&sh_cnt[2], c2);
        }
    }
    __syncthreads();
    if (tid == 0) {
        float tau; int ok = 1;
        if      (sh_cnt[0] >= K_) tau = tcand[0];
        else if (sh_cnt[1] >= K_) tau = tcand[1];
        else if (sh_cnt[2] >= K_) tau = tcand[2];
        else { ok = 0; tau = 0.0f; }
        sh_win = tau - 0.7032f;        // ln2 + fp-rounding margin
        if (!ok) sh_fb = 1;
    }
    __syncthreads();

    // ---- ordered compaction of candidates {q >= win} ----
    if (!sh_fb) {
        float win = sh_win;
        for (int start = 0; start < N_; start += TPB_*4) {
            int i0 = start + tid*4;
            int f0_=0, f1_=0, f2_=0, f3_=0;
            if (i0 + 3 < N_) {
                float4 vv = *(const float4*)(q + i0);
                f0_ = vv.x >= win; f1_ = vv.y >= win; f2_ = vv.z >= win; f3_ = vv.w >= win;
            } else {
                if (i0+0 < N_) f0_ = q[i0+0] >= win;
                if (i0+1 < N_) f1_ = q[i0+1] >= win;
                if (i0+2 < N_) f2_ = q[i0+2] >= win;
                if (i0+3 < N_) f3_ = q[i0+3] >= win;
            }
            int cnt = f0_+f1_+f2_+f3_;
            int lane = tid & 31, w = tid >> 5;
            int pre = cnt;
            for (int d = 1; d < 32; d <<= 1) {
                int t = __shfl_up_sync(0xFFFFFFFFu, pre, d);
                if (lane >= d) pre += t;
            }
            if (lane == 31) wtot[w] = pre;
            __syncthreads();
            int wbase = 0;
            #pragma unroll
            for (int x = 0; x < 16; x++) wbase += (x < w) ? wtot[x] : 0;
            int pos = sh_ncand + wbase + pre - cnt;
            if (f0_) { if (pos < CAP_) cidx[pos] = i0;   pos++; }
            if (f1_) { if (pos < CAP_) cidx[pos] = i0+1; pos++; }
            if (f2_) { if (pos < CAP_) cidx[pos] = i0+2; pos++; }
            if (f3_) { if (pos < CAP_) cidx[pos] = i0+3; pos++; }
            __syncthreads();
            if (tid == 0) { int t = 0; for (int x = 0; x < 16; x++) t += wtot[x]; sh_ncand += t; }
            __syncthreads();
        }
        if (tid == 0 && sh_ncand > CAP_) sh_fb = 1;
        __syncthreads();
    }

    if (!sh_fb) {
        int ncand = sh_ncand;
        // exact scores for candidates only (few hundred MUFUs)
        for (int j = tid; j < CAP_; j += TPB_) su[j] = 0ULL;
        __syncthreads();
        for (int j = tid; j < ncand; j += TPB_) {
            int n = cidx[j];
            int l = (n >= 5415) ? 2 : ((n >= 1083) ? 1 : 0);
            int gg = c_gg[l], noff = c_noff[l];
            int rel = n - noff;
            int cell = rel / 3, a = rel - cell*3;
            float p = feats[l][((size_t)(b*255 + a*85 + 5 + c))*gg + cell];
            float conf = g_conf_s[(size_t)b*N_ + noff + a*gg + cell];
            float s = conf * sigmoidf_(p);
            su[j] = (((unsigned long long)__float_as_uint(s)) << 32)
                  | (unsigned long long)(0xFFFFFFFFu - (uint32_t)j);
        }
        __syncthreads();
        int P = 128; while (P < ncand) P <<= 1;
        for (int k = 2; k <= P; k <<= 1)
            for (int j = k >> 1; j > 0; j >>= 1) {
                for (int m = tid; m < P; m += TPB_) {
                    int ixj = m ^ j;
                    if (ixj > m) {
                        unsigned long long A = su[m], Bv = su[ixj];
                        bool up = ((m & k) == 0);
                        if (up ? (A < Bv) : (A > Bv)) { su[m] = Bv; su[ixj] = A; }
                    }
                }
                __syncthreads();
            }
        if (tid < K_) {
            unsigned long long sv = su[tid];
            float s = __uint_as_float((uint32_t)(sv >> 32));
            int j = (int)(0xFFFFFFFFu - (uint32_t)sv);
            int n = cidx[j];
            g_top_s[(size_t)blk*K_ + tid] = s;
            const float* bx = &g_boxes[((size_t)b*N_ + n)*4];
            float* ob = &g_top_b[((size_t)blk*K_ + tid)*4];
            ob[0]=bx[0]; ob[1]=bx[1]; ob[2]=bx[2]; ob[3]=bx[3];
        }
    } else {
        // ---- exact fallback (rare): full scores + 100x argmax ----
        for (int l = 0; l < 3; l++) {
            int gg = c_gg[l], noff = c_noff[l];
            for (int a = 0; a < 3; a++) {
                const float* pp  = feats[l] + ((size_t)(b*255 + a*85 + 5 + c)) * gg;
                const float* cfp = g_conf_s + (size_t)b*N_ + noff + a*gg;
                for (int i = tid; i < gg; i += TPB_)
                    q[noff + i*3 + a] = cfp[i] * sigmoidf_(pp[i]);
            }
        }
        for (int i = tid; i < 712; i += TPB_) bmp[i] = 0;
        __syncthreads();
        for (int rr = 0; rr < K_; rr++) {
            unsigned long long best = 0ULL;
            for (int i = tid; i < N_; i += TPB_) {
                if (!((bmp[i>>5] >> (i & 31)) & 1u)) {
                    unsigned long long kk =
                        (((unsigned long long)__float_as_uint(q[i])) << 32)
                        | (unsigned long long)(0xFFFFFFFFu - (uint32_t)i);
                    best = (kk > best) ? kk : best;
                }
            }
            for (int d = 16; d; d >>= 1) {
                unsigned long long o = __shfl_down_sync(0xFFFFFFFFu, best, d);
                best = (o > best) ? o : best;
            }
            if ((tid & 31) == 0) wmax[tid >> 5] = best;
            __syncthreads();
            if (tid == 0) {
                unsigned long long bb = 0ULL;
                for (int x = 0; x < 16; x++) bb = (wmax[x] > bb) ? wmax[x] : bb;
                int n = (int)(0xFFFFFFFFu - (uint32_t)bb);
                bmp[n>>5] |= (1u << (n & 31));
                g_top_s[(size_t)blk*K_ + rr] = __uint_as_float((uint32_t)(bb >> 32));
                const float* bx = &g_boxes[((size_t)b*N_ + n)*4];
                float* ob = &g_top_b[((size_t)blk*K_ + rr)*4];
                ob[0]=bx[0]; ob[1]=bx[1]; ob[2]=bx[2]; ob[3]=bx[3];
            }
            __syncthreads();
        }
    }
}

// ---------------- stage 3: greedy NMS per (b,c) -----------------------------
__global__ void nms_kernel() {
    __shared__ float y1s[K_], x1s[K_], y2s[K_], x2s[K_], ars[K_], scs[K_];
    __shared__ unsigned char vld[K_], sup[K_];
    int blk = blockIdx.x;
    int tid = threadIdx.x;

    if (tid < K_) {
        const float* bx = &g_top_b[((size_t)blk*K_ + tid)*4];
        float a0 = bx[0], a1 = bx[1], a2 = bx[2], a3 = bx[3];
        y1s[tid] = a0; x1s[tid] = a1; y2s[tid] = a2; x2s[tid] = a3;
        ars[tid] = fmaxf(a2 - a0, 0.f) * fmaxf(a3 - a1, 0.f);
        float s = g_top_s[(size_t)blk*K_ + tid];
        scs[tid] = s;
        vld[tid] = (s >= 0.2f) ? 1 : 0;
        sup[tid] = 0;
    }
    __syncthreads();

    for (int i = 0; i < K_; i++) {
        bool keep_i = vld[i] && !sup[i];
        if (keep_i && tid > i && tid < K_) {
            float iy1 = fmaxf(y1s[i], y1s[tid]);
            float ix1 = fmaxf(x1s[i], x1s[tid]);
            float iy2 = fminf(y2s[i], y2s[tid]);
            float ix2 = fminf(x2s[i], x2s[tid]);
            float inter = fmaxf(iy2 - iy1, 0.f) * fmaxf(ix2 - ix1, 0.f);
            float iou = inter / (ars[i] + ars[tid] - inter + 1e-9f);
            if (iou > 0.3f) sup[tid] = 1;
        }
        __syncthreads();
    }

    if (tid < K_)
        g_cand[(size_t)blk*K_ + tid] = (vld[tid] && !sup[tid]) ? scs[tid] : -1.0f;
}

// ---------------- stage 4: per-image top-100 (full bitonic, exact ties) -----
__global__ __launch_bounds__(TPB_) void final_kernel(float* __restrict__ out) {
    extern __shared__ unsigned long long fs[];    // 8192 keys
    int tid = threadIdx.x, b = blockIdx.x;
    for (int i = tid; i < 8192; i += TPB_) {
        unsigned long long key = 0ULL;
        if (i < M_) {
            uint32_t u = __float_as_uint(g_cand[(size_t)b*M_ + i]);
            uint32_t m = (u & 0x80000000u) ? ~u : (u | 0x80000000u);
            key = (((unsigned long long)m) << 32)
                | (unsigned long long)(0xFFFFFFFFu - (uint32_t)i);
        }
        fs[i] = key;
    }
    __syncthreads();
    for (int k = 2; k <= 8192; k <<= 1)
        for (int j = k >> 1; j > 0; j >>= 1) {
            for (int m = tid; m < 8192; m += TPB_) {
                int ixj = m ^ j;
                if (ixj > m) {
                    unsigned long long A = fs[m], Bv = fs[ixj];
                    bool up = ((m & k) == 0);
                    if (up ? (A < Bv) : (A > Bv)) { fs[m] = Bv; fs[ixj] = A; }
                }
            }
            __syncthreads();
        }
    if (tid < K_) {
        unsigned long long sv = fs[tid];
        int idx = (int)(0xFFFFFFFFu - (uint32_t)sv);
        uint32_t m = (uint32_t)(sv >> 32);
        uint32_t ubits = (m & 0x80000000u) ? (m & 0x7FFFFFFFu) : ~m;
        const float* bx = &g_top_b[((size_t)b*M_ + idx)*4];
        float* o = out + ((size_t)b*K_ + tid)*6;
        o[0]=bx[0]; o[1]=bx[1]; o[2]=bx[2]; o[3]=bx[3];
        o[4] = __uint_as_float(ubits);
        o[5] = (float)(idx / K_);
    }
}

// ---------------- launch -----------------------------------------------------
extern "C" void kernel_launch(void* const* d_in, const int* in_sizes, int n_in,
                              void* d_out, int out_size) {
    const float* f0      = (const float*)d_in[0];
    const float* f1      = (const float*)d_in[1];
    const float* f2      = (const float*)d_in[2];
    const float* anchors = (const float*)d_in[3];
    const float* imshape = (const float*)d_in[4];
    float* out = (float*)d_out;

    cudaFuncSetAttribute(topk_kernel, cudaFuncAttributeMaxDynamicSharedMemorySize, SMEM_TOPK);
    cudaFuncSetAttribute(final_kernel, cudaFuncAttributeMaxDynamicSharedMemorySize, 8192*8);

    decode_kernel<<<(B_*CELLS_ + 255)/256, 256>>>(f0, f1, f2, anchors, imshape);
    topk_kernel<<<B_*C_, TPB_, SMEM_TOPK>>>(f0, f1, f2);
    nms_kernel<<<B_*C_, 128>>>();
    final_kernel<<<B_, TPB_, 8192*8>>>(out);
}

// round 4
// speedup vs baseline: 1.0010x; 1.0010x over previous
#include <cuda_runtime.h>
#include <math.h>
#include <stdint.h>

#define B_ 16
#define C_ 80
#define N_ 22743          // 3*(361 + 1444 + 5776)
#define K_ 100
#define CELLS_ 7581
#define M_ (C_*K_)        // 8000
#define CAP_ 3072
#define TPB_ 512

// smem layout offsets for topk (bytes)
#define Q_BYTES   90976                 // N_*4 rounded to 16
#define CIDX_OFF  Q_BYTES               // CAP_ ints = 12288
#define BMP_OFF   (Q_BYTES + CAP_*4)    // 712 u32 = 2848
#define SMEM_TOPK (BMP_OFF + 2848)      // 106112

// ---------------- scratch (device globals; no allocations allowed) ----------
__device__ float g_boxes[B_*N_*4];
__device__ float g_conf_s[B_*N_];       // segment layout: noff + a*gg + cell
__device__ float g_lc_s[B_*N_];         // log(conf), same layout
__device__ float g_top_s[B_*M_];
__device__ float g_top_b[B_*M_*4];
__device__ float g_cand[B_*M_];

__constant__ int c_gg[3]   = {361, 1444, 5776};
__constant__ int c_noff[3] = {0, 1083, 5415};

__device__ __forceinline__ float sigmoidf_(float x) { return 1.0f/(1.0f+expf(-x)); }

// ---------------- stage 1: decode boxes + conf + lc -------------------------
__global__ void decode_kernel(const float* __restrict__ f0, const float* __restrict__ f1,
                              const float* __restrict__ f2, const float* __restrict__ anchors,
                              const float* __restrict__ imshape) {
    int tid = blockIdx.x * blockDim.x + threadIdx.x;
    if (tid >= B_*CELLS_) return;
    int b  = tid / CELLS_;
    int cp = tid % CELLS_;

    const float* feat; int g, l, noff, coff;
    if (cp < 361)        { feat = f0; g = 19; l = 0; noff = 0;    coff = 0;    }
    else if (cp < 1805)  { feat = f1; g = 38; l = 1; noff = 1083; coff = 361;  }
    else                 { feat = f2; g = 76; l = 2; noff = 5415; coff = 1805; }

    int cell = cp - coff;
    int gg = g * g;
    int gy = cell / g, gx = cell % g;

    float imh = imshape[0], imw = imshape[1];
    const float ih = 608.0f, iw = 608.0f;
    float r  = fminf(ih/imh, iw/imw);
    float nh = rintf(imh*r), nw = rintf(imw*r);
    float offy = (ih - nh) * 0.5f / ih, offx = (iw - nw) * 0.5f / iw;
    float scy  = ih / nh,               scx  = iw / nw;

    #pragma unroll
    for (int a = 0; a < 3; a++) {
        const float* base = feat + ((size_t)b*255 + a*85) * (size_t)gg + cell;
        float tx = base[0];
        float ty = base[(size_t)gg];
        float tw = base[2*(size_t)gg];
        float th = base[3*(size_t)gg];
        float to = base[4*(size_t)gg];
        float conf = sigmoidf_(to);
        float lc   = -log1pf(expf(-to));       // log(sigmoid(to)), stable

        float bx = (sigmoidf_(tx) + (float)gx) / (float)g;
        float by = (sigmoidf_(ty) + (float)gy) / (float)g;
        int aidx = (2 - l)*3 + a;
        float bw = expf(tw) * anchors[aidx*2 + 0] / ih;
        float bh = expf(th) * anchors[aidx*2 + 1] / iw;

        float y  = (by - offy) * scy;
        float x  = (bx - offx) * scx;
        float hh = bh * scy;
        float ww = bw * scx;

        int n = noff + cell*3 + a;
        float* ob = &g_boxes[((size_t)b*N_ + n)*4];
        ob[0] = (y - hh*0.5f) * imh;
        ob[1] = (x - ww*0.5f) * imw;
        ob[2] = (y + hh*0.5f) * imh;
        ob[3] = (x + ww*0.5f) * imw;

        int np = noff + a*gg + cell;           // segment layout
        g_conf_s[(size_t)b*N_ + np] = conf;
        g_lc_s[(size_t)b*N_ + np]   = lc;
    }
}

// ---------------- stage 2: per-(b,c) exact top-100 via q-screen -------------
__global__ __launch_bounds__(TPB_) void topk_kernel(const float* __restrict__ f0,
                                                    const float* __restrict__ f1,
                                                    const float* __restrict__ f2) {
    extern __shared__ char sm[];
    float* q = (float*)sm;                                        // N_ floats
    int*   cidx = (int*)(sm + CIDX_OFF);                          // CAP_ ints
    uint32_t* samp = (uint32_t*)(sm + CIDX_OFF);                  // overlay (512 u32)
    unsigned long long* su = (unsigned long long*)sm;             // overlay (CAP_ u64 <= Q_BYTES)
    uint32_t* bmp = (uint32_t*)(sm + BMP_OFF);                    // 712 u32 (fallback)

    __shared__ int wtot[16];
    __shared__ unsigned long long wmax[16];
    __shared__ int sh_cnt[3];
    __shared__ float sh_win;
    __shared__ int sh_ncand, sh_fb;

    int tid = threadIdx.x;
    int blk = blockIdx.x;
    int b = blk / C_, c = blk % C_;
    const float* feats[3] = {f0, f1, f2};

    // ---- phase 1: compute screen key q[n] = min(p,0) + lc  (no MUFU) ----
    for (int l = 0; l < 3; l++) {
        int gg = c_gg[l], noff = c_noff[l];
        for (int a = 0; a < 3; a++) {
            const float* pp  = feats[l] + ((size_t)(b*255 + a*85 + 5 + c)) * gg;
            const float* lcp = g_lc_s + (size_t)b*N_ + noff + a*gg;
            for (int i = tid; i < gg; i += TPB_)
                q[noff + i*3 + a] = fminf(pp[i], 0.0f) + lcp[i];
        }
    }
    __syncthreads();

    // ---- sample 512 keys, bitonic sort desc (mapped uint order) ----
    {
        float v = q[tid*44 + 17];
        uint32_t u = __float_as_uint(v);
        samp[tid] = (u & 0x80000000u) ? ~u : (u | 0x80000000u);
    }
    __syncthreads();
    for (int k = 2; k <= 512; k <<= 1)
        for (int j = k >> 1; j > 0; j >>= 1) {
            int ixj = tid ^ j;
            if (ixj > tid) {
                uint32_t A = samp[tid], Bv = samp[ixj];
                bool up = ((tid & k) == 0);
                if (up ? (A < Bv) : (A > Bv)) { samp[tid] = Bv; samp[ixj] = A; }
            }
            __syncthreads();
        }

    float tcand[3];
    {
        const int rr0 = 3, rr1 = 7, rr2 = 15;
        uint32_t us[3] = { samp[rr0], samp[rr1], samp[rr2] };
        #pragma unroll
        for (int t = 0; t < 3; t++) {
            uint32_t u = us[t];
            uint32_t bits = (u & 0x80000000u) ? (u & 0x7FFFFFFFu) : ~u;
            tcand[t] = __uint_as_float(bits);
        }
    }
    if (tid < 3) sh_cnt[tid] = 0;
    if (tid == 0) { sh_fb = 0; sh_ncand = 0; }
    __syncthreads();

    // ---- verify pass: count 3 thresholds (ballot-free, no hot atomics) ----
    {
        int c0 = 0, c1 = 0, c2 = 0;
        for (int i = tid; i < N_; i += TPB_) {
            float v = q[i];
            c0 += (v >= tcand[0]); c1 += (v >= tcand[1]); c2 += (v >= tcand[2]);
        }
        for (int d = 16; d; d >>= 1) {
            c0 += __shfl_down_sync(0xFFFFFFFFu, c0, d);
            c1 += __shfl_down_sync(0xFFFFFFFFu, c1, d);
            c2 += __shfl_down_sync(0xFFFFFFFFu, c2, d);
        }
        if ((tid & 31) == 0) {
            atomicAdd(&sh_cnt[0], c0); atomicAdd(&sh_cnt[1], c1); atomicAdd(&sh_cnt[2], c2);
        }
    }
    __syncthreads();
    if (tid == 0) {
        float tau; int ok = 1;
        if      (sh_cnt[0] >= K_) tau = tcand[0];
        else if (sh_cnt[1] >= K_) tau = tcand[1];
        else if (sh_cnt[2] >= K_) tau = tcand[2];
        else { ok = 0; tau = 0.0f; }
        sh_win = tau - 0.7032f;        // ln2 + fp-rounding margin
        if (!ok) sh_fb = 1;
    }
    __syncthreads();

    // ---- ordered compaction of candidates {q >= win} ----
    if (!sh_fb) {
        float win = sh_win;
        for (int start = 0; start < N_; start += TPB_*4) {
            int i0 = start + tid*4;
            int f0_=0, f1_=0, f2_=0, f3_=0;
            if (i0 + 3 < N_) {
                float4 vv = *(const float4*)(q + i0);
                f0_ = vv.x >= win; f1_ = vv.y >= win; f2_ = vv.z >= win; f3_ = vv.w >= win;
            } else {
                if (i0+0 < N_) f0_ = q[i0+0] >= win;
                if (i0+1 < N_) f1_ = q[i0+1] >= win;
                if (i0+2 < N_) f2_ = q[i0+2] >= win;
                if (i0+3 < N_) f3_ = q[i0+3] >= win;
            }
            int cnt = f0_+f1_+f2_+f3_;
            int lane = tid & 31, w = tid >> 5;
            int pre = cnt;
            for (int d = 1; d < 32; d <<= 1) {
                int t = __shfl_up_sync(0xFFFFFFFFu, pre, d);
                if (lane >= d) pre += t;
            }
            if (lane == 31) wtot[w] = pre;
            __syncthreads();
            int wbase = 0;
            #pragma unroll
            for (int x = 0; x < 16; x++) wbase += (x < w) ? wtot[x] : 0;
            int pos = sh_ncand + wbase + pre - cnt;
            if (f0_) { if (pos < CAP_) cidx[pos] = i0;   pos++; }
            if (f1_) { if (pos < CAP_) cidx[pos] = i0+1; pos++; }
            if (f2_) { if (pos < CAP_) cidx[pos] = i0+2; pos++; }
            if (f3_) { if (pos < CAP_) cidx[pos] = i0+3; pos++; }
            __syncthreads();
            if (tid == 0) { int t = 0; for (int x = 0; x < 16; x++) t += wtot[x]; sh_ncand += t; }
            __syncthreads();
        }
        if (tid == 0 && sh_ncand > CAP_) sh_fb = 1;
        __syncthreads();
    }

    if (!sh_fb) {
        int ncand = sh_ncand;
        // exact scores for candidates only (few hundred MUFUs)
        for (int j = tid; j < CAP_; j += TPB_) su[j] = 0ULL;
        __syncthreads();
        for (int j = tid; j < ncand; j += TPB_) {
            int n = cidx[j];
            int l = (n >= 5415) ? 2 : ((n >= 1083) ? 1 : 0);
            int gg = c_gg[l], noff = c_noff[l];
            int rel = n - noff;
            int cell = rel / 3, a = rel - cell*3;
            float p = feats[l][((size_t)(b*255 + a*85 + 5 + c))*gg + cell];
            float conf = g_conf_s[(size_t)b*N_ + noff + a*gg + cell];
            float s = conf * sigmoidf_(p);
            su[j] = (((unsigned long long)__float_as_uint(s)) << 32)
                  | (unsigned long long)(0xFFFFFFFFu - (uint32_t)j);
        }
        __syncthreads();
        int P = 128; while (P < ncand) P <<= 1;
        for (int k = 2; k <= P; k <<= 1)
            for (int j = k >> 1; j > 0; j >>= 1) {
                for (int m = tid; m < P; m += TPB_) {
                    int ixj = m ^ j;
                    if (ixj > m) {
                        unsigned long long A = su[m], Bv = su[ixj];
                        bool up = ((m & k) == 0);
                        if (up ? (A < Bv) : (A > Bv)) { su[m] = Bv; su[ixj] = A; }
                    }
                }
                __syncthreads();
            }
        if (tid < K_) {
            unsigned long long sv = su[tid];
            float s = __uint_as_float((uint32_t)(sv >> 32));
            int j = (int)(0xFFFFFFFFu - (uint32_t)sv);
            int n = cidx[j];
            g_top_s[(size_t)blk*K_ + tid] = s;
            const float* bx = &g_boxes[((size_t)b*N_ + n)*4];
            float* ob = &g_top_b[((size_t)blk*K_ + tid)*4];
            ob[0]=bx[0]; ob[1]=bx[1]; ob[2]=bx[2]; ob[3]=bx[3];
        }
    } else {
        // ---- exact fallback (rare): full scores + 100x argmax ----
        for (int l = 0; l < 3; l++) {
            int gg = c_gg[l], noff = c_noff[l];
            for (int a = 0; a < 3; a++) {
                const float* pp  = feats[l] + ((size_t)(b*255 + a*85 + 5 + c)) * gg;
                const float* cfp = g_conf_s + (size_t)b*N_ + noff + a*gg;
                for (int i = tid; i < gg; i += TPB_)
                    q[noff + i*3 + a] = cfp[i] * sigmoidf_(pp[i]);
            }
        }
        for (int i = tid; i < 712; i += TPB_) bmp[i] = 0;
        __syncthreads();
        for (int rr = 0; rr < K_; rr++) {
            unsigned long long best = 0ULL;
            for (int i = tid; i < N_; i += TPB_) {
                if (!((bmp[i>>5] >> (i & 31)) & 1u)) {
                    unsigned long long kk =
                        (((unsigned long long)__float_as_uint(q[i])) << 32)
                        | (unsigned long long)(0xFFFFFFFFu - (uint32_t)i);
                    best = (kk > best) ? kk : best;
                }
            }
            for (int d = 16; d; d >>= 1) {
                unsigned long long o = __shfl_down_sync(0xFFFFFFFFu, best, d);
                best = (o > best) ? o : best;
            }
            if ((tid & 31) == 0) wmax[tid >> 5] = best;
            __syncthreads();
            if (tid == 0) {
                unsigned long long bb = 0ULL;
                for (int x = 0; x < 16; x++) bb = (wmax[x] > bb) ? wmax[x] : bb;
                int n = (int)(0xFFFFFFFFu - (uint32_t)bb);
                bmp[n>>5] |= (1u << (n & 31));
                g_top_s[(size_t)blk*K_ + rr] = __uint_as_float((uint32_t)(bb >> 32));
                const float* bx = &g_boxes[((size_t)b*N_ + n)*4];
                float* ob = &g_top_b[((size_t)blk*K_ + rr)*4];
                ob[0]=bx[0]; ob[1]=bx[1]; ob[2]=bx[2]; ob[3]=bx[3];
            }
            __syncthreads();
        }
    }
}

// ---------------- stage 3: greedy NMS per (b,c) -----------------------------
__global__ void nms_kernel() {
    __shared__ float y1s[K_], x1s[K_], y2s[K_], x2s[K_], ars[K_], scs[K_];
    __shared__ unsigned char vld[K_], sup[K_];
    int blk = blockIdx.x;
    int tid = threadIdx.x;

    if (tid < K_) {
        const float* bx = &g_top_b[((size_t)blk*K_ + tid)*4];
        float a0 = bx[0], a1 = bx[1], a2 = bx[2], a3 = bx[3];
        y1s[tid] = a0; x1s[tid] = a1; y2s[tid] = a2; x2s[tid] = a3;
        ars[tid] = fmaxf(a2 - a0, 0.f) * fmaxf(a3 - a1, 0.f);
        float s = g_top_s[(size_t)blk*K_ + tid];
        scs[tid] = s;
        vld[tid] = (s >= 0.2f) ? 1 : 0;
        sup[tid] = 0;
    }
    __syncthreads();

    for (int i = 0; i < K_; i++) {
        bool keep_i = vld[i] && !sup[i];
        if (keep_i && tid > i && tid < K_) {
            float iy1 = fmaxf(y1s[i], y1s[tid]);
            float ix1 = fmaxf(x1s[i], x1s[tid]);
            float iy2 = fminf(y2s[i], y2s[tid]);
            float ix2 = fminf(x2s[i], x2s[tid]);
            float inter = fmaxf(iy2 - iy1, 0.f) * fmaxf(ix2 - ix1, 0.f);
            float iou = inter / (ars[i] + ars[tid] - inter + 1e-9f);
            if (iou > 0.3f) sup[tid] = 1;
        }
        __syncthreads();
    }

    if (tid < K_)
        g_cand[(size_t)blk*K_ + tid] = (vld[tid] && !sup[tid]) ? scs[tid] : -1.0f;
}

// ---------------- stage 4: per-image top-100 (full bitonic, exact ties) -----
__global__ __launch_bounds__(TPB_) void final_kernel(float* __restrict__ out) {
    extern __shared__ unsigned long long fs[];    // 8192 keys
    int tid = threadIdx.x, b = blockIdx.x;
    for (int i = tid; i < 8192; i += TPB_) {
        unsigned long long key = 0ULL;
        if (i < M_) {
            uint32_t u = __float_as_uint(g_cand[(size_t)b*M_ + i]);
            uint32_t m = (u & 0x80000000u) ? ~u : (u | 0x80000000u);
            key = (((unsigned long long)m) << 32)
                | (unsigned long long)(0xFFFFFFFFu - (uint32_t)i);
        }
        fs[i] = key;
    }
    __syncthreads();
    for (int k = 2; k <= 8192; k <<= 1)
        for (int j = k >> 1; j > 0; j >>= 1) {
            for (int m = tid; m < 8192; m += TPB_) {
                int ixj = m ^ j;
                if (ixj > m) {
                    unsigned long long A = fs[m], Bv = fs[ixj];
                    bool up = ((m & k) == 0);
                    if (up ? (A < Bv) : (A > Bv)) { fs[m] = Bv; fs[ixj] = A; }
                }
            }
            __syncthreads();
        }
    if (tid < K_) {
        unsigned long long sv = fs[tid];
        int idx = (int)(0xFFFFFFFFu - (uint32_t)sv);
        uint32_t m = (uint32_t)(sv >> 32);
        uint32_t ubits = (m & 0x80000000u) ? (m & 0x7FFFFFFFu) : ~m;
        const float* bx = &g_top_b[((size_t)b*M_ + idx)*4];
        float* o = out + ((size_t)b*K_ + tid)*6;
        o[0]=bx[0]; o[1]=bx[1]; o[2]=bx[2]; o[3]=bx[3];
        o[4] = __uint_as_float(ubits);
        o[5] = (float)(idx / K_);
    }
}

// ---------------- launch -----------------------------------------------------
extern "C" void kernel_launch(void* const* d_in, const int* in_sizes, int n_in,
                              void* d_out, int out_size) {
    const float* f0      = (const float*)d_in[0];
    const float* f1      = (const float*)d_in[1];
    const float* f2      = (const float*)d_in[2];
    const float* anchors = (const float*)d_in[3];
    const float* imshape = (const float*)d_in[4];
    float* out = (float*)d_out;

    cudaFuncSetAttribute(topk_kernel, cudaFuncAttributeMaxDynamicSharedMemorySize, SMEM_TOPK);
    cudaFuncSetAttribute(final_kernel, cudaFuncAttributeMaxDynamicSharedMemorySize, 8192*8);

    decode_kernel<<<(B_*CELLS_ + 255)/256, 256>>>(f0, f1, f2, anchors, imshape);
    topk_kernel<<<B_*C_, TPB_, SMEM_TOPK>>>(f0, f1, f2);
    nms_kernel<<<B_*C_, 128>>>();
    final_kernel<<<B_, TPB_, 8192*8>>>(out);
}

// round 5
// speedup vs baseline: 6.3335x; 6.3273x over previous
#include <cuda_runtime.h>
#include <math.h>
#include <stdint.h>

#define B_ 16
#define C_ 80
#define N_ 22743
#define K_ 100
#define CELLS_ 7581
#define M_ (C_*K_)
#define CAP_ 2048
#define PADTOT_ 22752
#define GP_ 5688          // 3*(91+361+1444) float4-groups per image
#define NSAMP_ 8192

__device__ float g_boxes[B_*N_*4];
__device__ float g_conf_p[B_*PADTOT_];
__device__ float g_pth[B_*PADTOT_];
__device__ float g_tau[B_];
__device__ int   g_ccnt[B_*C_];
__device__ int   g_clist[(size_t)B_*C_*CAP_];
__device__ int   g_fbf[B_*C_];
__device__ float g_top_s[B_*M_];
__device__ float g_top_b[B_*M_*4];
__device__ float g_cand[B_*M_];

__constant__ int c_gg[3]   = {361,1444,5776};
__constant__ int c_noff[3] = {0,1083,5415};
__constant__ int c_soff[9] = {0,364,728,1092,2536,3980,5424,11200,16976};

__device__ __forceinline__ float sigmoidf_(float x){ return 1.0f/(1.0f+expf(-x)); }

__global__ void zero_kernel(){
    for (int i = threadIdx.x; i < B_*C_; i += 512){ g_ccnt[i]=0; g_fbf[i]=0; }
}

// ---------------- decode: boxes + conf --------------------------------------
__global__ void decode_kernel(const float* __restrict__ f0, const float* __restrict__ f1,
                              const float* __restrict__ f2, const float* __restrict__ anchors,
                              const float* __restrict__ imshape){
    int tid = blockIdx.x*blockDim.x + threadIdx.x;
    if (tid >= B_*CELLS_) return;
    int b = tid / CELLS_, cp = tid % CELLS_;
    const float* feat; int g,l,noff,coff;
    if (cp < 361)       { feat=f0; g=19; l=0; noff=0;    coff=0;    }
    else if (cp < 1805) { feat=f1; g=38; l=1; noff=1083; coff=361;  }
    else                { feat=f2; g=76; l=2; noff=5415; coff=1805; }
    int cell = cp - coff, gg = g*g;
    int gy = cell/g, gx = cell%g;

    float imh = imshape[0], imw = imshape[1];
    const float ih = 608.0f, iw = 608.0f;
    float r  = fminf(ih/imh, iw/imw);
    float nh = rintf(imh*r), nw = rintf(imw*r);
    float offy = (ih-nh)*0.5f/ih, offx = (iw-nw)*0.5f/iw;
    float scy = ih/nh, scx = iw/nw;

    #pragma unroll
    for (int a = 0; a < 3; a++){
        const float* base = feat + ((size_t)b*255 + a*85)*(size_t)gg + cell;
        float tx = base[0], ty = base[(size_t)gg], tw = base[2*(size_t)gg];
        float th = base[3*(size_t)gg], to = base[4*(size_t)gg];
        float conf = sigmoidf_(to);
        float bx = (sigmoidf_(tx) + (float)gx)/(float)g;
        float by = (sigmoidf_(ty) + (float)gy)/(float)g;
        int aidx = (2-l)*3 + a;
        float bw = expf(tw)*anchors[aidx*2+0]/ih;
        float bh = expf(th)*anchors[aidx*2+1]/iw;
        float y = (by-offy)*scy, x = (bx-offx)*scx;
        float hh = bh*scy, ww = bw*scx;
        int n = noff + cell*3 + a;
        float* ob = &g_boxes[((size_t)b*N_ + n)*4];
        ob[0] = (y - hh*0.5f)*imh;
        ob[1] = (x - ww*0.5f)*imw;
        ob[2] = (y + hh*0.5f)*imh;
        ob[3] = (x + ww*0.5f)*imw;
        g_conf_p[(size_t)b*PADTOT_ + c_soff[l*3+a] + cell] = conf;
    }
}

// ---------------- per-image tau via 8192 exact samples -----------------------
__global__ void sample_kernel(const float* __restrict__ f0, const float* __restrict__ f1,
                              const float* __restrict__ f2){
    __shared__ float ss[NSAMP_];
    __shared__ int red[17];
    int b = blockIdx.x, tid = threadIdx.x;
    const float* feats[3] = {f0,f1,f2};
    for (int j = tid; j < NSAMP_; j += 512){
        uint32_t n = ((uint32_t)j*2654435761u + 971u) % N_;
        uint32_t c = ((uint32_t)j*48271u + 17u) % C_;
        int l = (n >= 5415) ? 2 : ((n >= 1083) ? 1 : 0);
        int rel = (int)n - c_noff[l];
        int cell = rel/3, a = rel - cell*3;
        float p = feats[l][((size_t)(b*255 + a*85 + 5 + (int)c))*c_gg[l] + cell];
        float conf = g_conf_p[(size_t)b*PADTOT_ + c_soff[l*3+a] + cell];
        ss[j] = conf * sigmoidf_(p);
    }
    __syncthreads();
    uint32_t lo = 0, hi = 0x3F800000u;
    for (int it = 0; it < 26; it++){
        float mv = __uint_as_float((lo + hi) >> 1);
        int cnt = 0;
        for (int j = tid; j < NSAMP_; j += 512) cnt += (ss[j] >= mv);
        for (int d = 16; d; d >>= 1) cnt += __shfl_down_sync(0xFFFFFFFFu, cnt, d);
        if ((tid & 31) == 0) red[tid >> 5] = cnt;
        __syncthreads();
        if (tid == 0){ int t=0; for (int w=0; w<16; w++) t += red[w]; red[16]=t; }
        __syncthreads();
        if (red[16] >= 144) lo = (lo+hi)>>1; else hi = (lo+hi)>>1;
        __syncthreads();
    }
    if (tid == 0) g_tau[b] = __uint_as_float(lo);
}

// ---------------- per-anchor p-threshold -------------------------------------
__global__ void pth_kernel(){
    int gid = blockIdx.x*blockDim.x + threadIdx.x;
    if (gid >= B_*PADTOT_) return;
    int b = gid / PADTOT_, s = gid % PADTOT_;
    int seg = 8;
    #pragma unroll
    for (int x = 1; x < 9; x++) if (s < c_soff[x]) { seg = x-1; break; }
    int l = seg/3, cell = s - c_soff[seg];
    float v = 1e30f;
    if (cell < c_gg[l]){
        float conf = g_conf_p[gid], tau = g_tau[b];
        if (conf > tau) v = logf(tau/(conf - tau)) - 3e-3f;
    }
    g_pth[gid] = v;
}

// ---------------- big scan: compare-only stream -------------------------------
__global__ __launch_bounds__(256) void scan_kernel(const float* __restrict__ f0,
                                                   const float* __restrict__ f1,
                                                   const float* __restrict__ f2){
    int gid = blockIdx.x*blockDim.x + threadIdx.x;
    if (gid >= B_*GP_) return;
    int b = gid / GP_, r = gid % GP_;
    int l, a, q;
    if (r < 273)       { l = 0; a = r/91;   q = r - a*91;   }
    else if (r < 1356) { int rr=r-273;  l = 1; a = rr/361;  q = rr - a*361;  }
    else               { int rr=r-1356; l = 2; a = rr/1444; q = rr - a*1444; }
    int cell = q*4, gg = c_gg[l], noff = c_noff[l];
    const float* f = (l==0) ? f0 : ((l==1) ? f1 : f2);

    float4 pth = *(const float4*)&g_pth[(size_t)b*PADTOT_ + c_soff[l*3+a] + cell];
    float minp = fminf(fminf(pth.x, pth.y), fminf(pth.z, pth.w));
    if (!(minp < 1e29f)) return;

    const float* base = f + ((size_t)(b*255 + a*85 + 5))*gg + cell;
    int bc0 = b*C_;
    if (l == 0){
        bool v1 = cell+1 < gg, v2 = cell+2 < gg, v3 = cell+3 < gg;
        for (int c = 0; c < C_; c++){
            const float* pp = base + (size_t)c*gg;
            float p0 = pp[0];
            float p1 = v1 ? pp[1] : -1e30f;
            float p2 = v2 ? pp[2] : -1e30f;
            float p3 = v3 ? pp[3] : -1e30f;
            if (p0>=pth.x || p1>=pth.y || p2>=pth.z || p3>=pth.w){
                int bc = bc0 + c;
                if (p0>=pth.x){ int o=atomicAdd(&g_ccnt[bc],1); if(o<CAP_) g_clist[(size_t)bc*CAP_+o]=noff+(cell+0)*3+a; }
                if (p1>=pth.y){ int o=atomicAdd(&g_ccnt[bc],1); if(o<CAP_) g_clist[(size_t)bc*CAP_+o]=noff+(cell+1)*3+a; }
                if (p2>=pth.z){ int o=atomicAdd(&g_ccnt[bc],1); if(o<CAP_) g_clist[(size_t)bc*CAP_+o]=noff+(cell+2)*3+a; }
                if (p3>=pth.w){ int o=atomicAdd(&g_ccnt[bc],1); if(o<CAP_) g_clist[(size_t)bc*CAP_+o]=noff+(cell+3)*3+a; }
            }
        }
    } else {
        #pragma unroll 4
        for (int c = 0; c < C_; c++){
            float4 p = *(const float4*)(base + (size_t)c*gg);
            if (p.x>=pth.x || p.y>=pth.y || p.z>=pth.z || p.w>=pth.w){
                int bc = bc0 + c;
                if (p.x>=pth.x){ int o=atomicAdd(&g_ccnt[bc],1); if(o<CAP_) g_clist[(size_t)bc*CAP_+o]=noff+(cell+0)*3+a; }
                if (p.y>=pth.y){ int o=atomicAdd(&g_ccnt[bc],1); if(o<CAP_) g_clist[(size_t)bc*CAP_+o]=noff+(cell+1)*3+a; }
                if (p.z>=pth.z){ int o=atomicAdd(&g_ccnt[bc],1); if(o<CAP_) g_clist[(size_t)bc*CAP_+o]=noff+(cell+2)*3+a; }
                if (p.w>=pth.w){ int o=atomicAdd(&g_ccnt[bc],1); if(o<CAP_) g_clist[(size_t)bc*CAP_+o]=noff+(cell+3)*3+a; }
            }
        }
    }
}

// ---------------- per-(b,c) exact top-100 from candidates --------------------
__global__ __launch_bounds__(256) void topc_kernel(const float* __restrict__ f0,
                                                   const float* __restrict__ f1,
                                                   const float* __restrict__ f2){
    __shared__ unsigned long long su[CAP_];
    __shared__ int s_ge;
    int blk = blockIdx.x, tid = threadIdx.x;
    int b = blk / C_, c = blk % C_;
    int cnt = g_ccnt[blk];
    if (cnt > CAP_){ if (tid == 0) g_fbf[blk] = 1; return; }
    float tau = g_tau[b];
    const float* feats[3] = {f0,f1,f2};

    if (tid == 0) s_ge = 0;
    for (int j = tid; j < CAP_; j += 256) su[j] = 0ULL;
    __syncthreads();

    int ge = 0;
    for (int j = tid; j < cnt; j += 256){
        int n = g_clist[(size_t)blk*CAP_ + j];
        int l = (n >= 5415) ? 2 : ((n >= 1083) ? 1 : 0);
        int rel = n - c_noff[l];
        int cell = rel/3, a = rel - cell*3;
        float p = feats[l][((size_t)(b*255 + a*85 + 5 + c))*c_gg[l] + cell];
        float conf = g_conf_p[(size_t)b*PADTOT_ + c_soff[l*3+a] + cell];
        float s = conf * sigmoidf_(p);
        ge += (s >= tau);
        su[j] = (((unsigned long long)__float_as_uint(s)) << 32)
              | (unsigned long long)(0xFFFFFFFFu - (uint32_t)n);
    }
    for (int d = 16; d; d >>= 1) ge += __shfl_down_sync(0xFFFFFFFFu, ge, d);
    if ((tid & 31) == 0) atomicAdd(&s_ge, ge);
    __syncthreads();
    if (s_ge < K_){ if (tid == 0) g_fbf[blk] = 1; return; }

    int P = 128; while (P < cnt) P <<= 1;
    for (int kk = 2; kk <= P; kk <<= 1)
        for (int j = kk >> 1; j > 0; j >>= 1){
            for (int m = tid; m < P; m += 256){
                int ixj = m ^ j;
                if (ixj > m){
                    unsigned long long A = su[m], Bv = su[ixj];
                    bool up = ((m & kk) == 0);
                    if (up ? (A < Bv) : (A > Bv)){ su[m] = Bv; su[ixj] = A; }
                }
            }
            __syncthreads();
        }
    if (tid < K_){
        unsigned long long sv = su[tid];
        int n = (int)(0xFFFFFFFFu - (uint32_t)sv);
        g_top_s[(size_t)blk*K_ + tid] = __uint_as_float((uint32_t)(sv >> 32));
        const float* bx = &g_boxes[((size_t)b*N_ + n)*4];
        float* ob = &g_top_b[((size_t)blk*K_ + tid)*4];
        ob[0]=bx[0]; ob[1]=bx[1]; ob[2]=bx[2]; ob[3]=bx[3];
    }
}

// ---------------- exact fallback for flagged blocks (rare) -------------------
__global__ __launch_bounds__(256) void fb_kernel(const float* __restrict__ f0,
                                                 const float* __restrict__ f1,
                                                 const float* __restrict__ f2){
    extern __shared__ char fsm[];
    float* q = (float*)fsm;                       // N_ floats
    uint32_t* bmp = (uint32_t*)(fsm + 90976);     // 712 u32
    __shared__ unsigned long long wmax[8];
    int blk = blockIdx.x, tid = threadIdx.x;
    if (!g_fbf[blk]) return;
    int b = blk / C_, c = blk % C_;
    const float* feats[3] = {f0,f1,f2};
    for (int l = 0; l < 3; l++){
        int gg = c_gg[l], noff = c_noff[l];
        for (int a = 0; a < 3; a++){
            const float* pp  = feats[l] + ((size_t)(b*255 + a*85 + 5 + c))*gg;
            const float* cfp = g_conf_p + (size_t)b*PADTOT_ + c_soff[l*3+a];
            for (int i = tid; i < gg; i += 256)
                q[noff + i*3 + a] = cfp[i] * sigmoidf_(pp[i]);
        }
    }
    for (int i = tid; i < 712; i += 256) bmp[i] = 0;
    __syncthreads();
    for (int rr = 0; rr < K_; rr++){
        unsigned long long best = 0ULL;
        for (int i = tid; i < N_; i += 256){
            if (!((bmp[i>>5] >> (i & 31)) & 1u)){
                unsigned long long kk = (((unsigned long long)__float_as_uint(q[i])) << 32)
                                      | (unsigned long long)(0xFFFFFFFFu - (uint32_t)i);
                best = (kk > best) ? kk : best;
            }
        }
        for (int d = 16; d; d >>= 1){
            unsigned long long o = __shfl_down_sync(0xFFFFFFFFu, best, d);
            best = (o > best) ? o : best;
        }
        if ((tid & 31) == 0) wmax[tid >> 5] = best;
        __syncthreads();
        if (tid == 0){
            unsigned long long bb = 0ULL;
            for (int x = 0; x < 8; x++) bb = (wmax[x] > bb) ? wmax[x] : bb;
            int n = (int)(0xFFFFFFFFu - (uint32_t)bb);
            bmp[n>>5] |= (1u << (n & 31));
            g_top_s[(size_t)blk*K_ + rr] = __uint_as_float((uint32_t)(bb >> 32));
            const float* bx = &g_boxes[((size_t)b*N_ + n)*4];
            float* ob = &g_top_b[((size_t)blk*K_ + rr)*4];
            ob[0]=bx[0]; ob[1]=bx[1]; ob[2]=bx[2]; ob[3]=bx[3];
        }
        __syncthreads();
    }
}

// ---------------- greedy NMS per (b,c) ---------------------------------------
__global__ void nms_kernel(){
    __shared__ float y1s[K_], x1s[K_], y2s[K_], x2s[K_], ars[K_], scs[K_];
    __shared__ unsigned char vld[K_], sup[K_];
    int blk = blockIdx.x, tid = threadIdx.x;
    if (tid < K_){
        const float* bx = &g_top_b[((size_t)blk*K_ + tid)*4];
        float a0=bx[0], a1=bx[1], a2=bx[2], a3=bx[3];
        y1s[tid]=a0; x1s[tid]=a1; y2s[tid]=a2; x2s[tid]=a3;
        ars[tid] = fmaxf(a2-a0, 0.f)*fmaxf(a3-a1, 0.f);
        float s = g_top_s[(size_t)blk*K_ + tid];
        scs[tid]=s; vld[tid]=(s >= 0.2f); sup[tid]=0;
    }
    __syncthreads();
    for (int i = 0; i < K_; i++){
        bool keep_i = vld[i] && !sup[i];
        if (keep_i && tid > i && tid < K_){
            float iy1=fmaxf(y1s[i],y1s[tid]), ix1=fmaxf(x1s[i],x1s[tid]);
            float iy2=fminf(y2s[i],y2s[tid]), ix2=fminf(x2s[i],x2s[tid]);
            float inter=fmaxf(iy2-iy1,0.f)*fmaxf(ix2-ix1,0.f);
            if (inter/(ars[i]+ars[tid]-inter+1e-9f) > 0.3f) sup[tid]=1;
        }
        __syncthreads();
    }
    if (tid < K_)
        g_cand[(size_t)blk*K_ + tid] = (vld[tid] && !sup[tid]) ? scs[tid] : -1.0f;
}

// ---------------- final per-image top-100: u64 binary search -----------------
__global__ __launch_bounds__(512) void final_kernel(float* __restrict__ out){
    __shared__ int red;
    __shared__ unsigned long long list[128];
    __shared__ int pos;
    int b = blockIdx.x, tid = threadIdx.x;
    unsigned long long key[16];
    #pragma unroll
    for (int j = 0; j < 16; j++){
        int i = tid + j*512;
        unsigned long long kk = 0ULL;
        if (i < M_){
            uint32_t u = __float_as_uint(g_cand[(size_t)b*M_ + i]);
            uint32_t m = (u & 0x80000000u) ? ~u : (u | 0x80000000u);
            kk = (((unsigned long long)m) << 32) | (unsigned long long)(0xFFFFFFFFu - (uint32_t)i);
        }
        key[j] = kk;
    }
    unsigned long long lo = 0ULL, hi = 0xFFFFFFFFFFFFFFFFULL;
    for (int it = 0; it < 64 && hi - lo > 1ULL; it++){
        unsigned long long mid = lo + ((hi - lo) >> 1);
        if (tid == 0) red = 0;
        __syncthreads();
        int c = 0;
        #pragma unroll
        for (int j = 0; j < 16; j++) c += (key[j] >= mid);
        for (int d = 16; d; d >>= 1) c += __shfl_down_sync(0xFFFFFFFFu, c, d);
        if ((tid & 31) == 0) atomicAdd(&red, c);
        __syncthreads();
        if (red >= K_) lo = mid; else hi = mid;
        __syncthreads();
    }
    if (tid == 0) pos = 0;
    if (tid < 128) list[tid] = 0ULL;
    __syncthreads();
    #pragma unroll
    for (int j = 0; j < 16; j++)
        if (key[j] >= lo){ int p = atomicAdd(&pos, 1); if (p < 128) list[p] = key[j]; }
    __syncthreads();
    for (int k = 2; k <= 128; k <<= 1)
        for (int j = k >> 1; j > 0; j >>= 1){
            if (tid < 128){
                int ixj = tid ^ j;
                if (ixj > tid){
                    unsigned long long A = list[tid], Bv = list[ixj];
                    bool up = ((tid & k) == 0);
                    if (up ? (A < Bv) : (A > Bv)){ list[tid] = Bv; list[ixj] = A; }
                }
            }
            __syncthreads();
        }
    if (tid < K_){
        unsigned long long sv = list[tid];
        int idx = (int)(0xFFFFFFFFu - (uint32_t)sv);
        uint32_t m = (uint32_t)(sv >> 32);
        uint32_t ub = (m & 0x80000000u) ? (m & 0x7FFFFFFFu) : ~m;
        const float* bx = &g_top_b[((size_t)b*M_ + idx)*4];
        float* o = out + ((size_t)b*K_ + tid)*6;
        o[0]=bx[0]; o[1]=bx[1]; o[2]=bx[2]; o[3]=bx[3];
        o[4] = __uint_as_float(ub);
        o[5] = (float)(idx / K_);
    }
}

extern "C" void kernel_launch(void* const* d_in, const int* in_sizes, int n_in,
                              void* d_out, int out_size){
    const float* f0      = (const float*)d_in[0];
    const float* f1      = (const float*)d_in[1];
    const float* f2      = (const float*)d_in[2];
    const float* anchors = (const float*)d_in[3];
    const float* imshape = (const float*)d_in[4];
    float* out = (float*)d_out;

    cudaFuncSetAttribute(fb_kernel, cudaFuncAttributeMaxDynamicSharedMemorySize, 93824);

    zero_kernel<<<1, 512>>>();
    decode_kernel<<<(B_*CELLS_ + 255)/256, 256>>>(f0, f1, f2, anchors, imshape);
    sample_kernel<<<B_, 512>>>(f0, f1, f2);
    pth_kernel<<<(B_*PADTOT_ + 255)/256, 256>>>();
    scan_kernel<<<(B_*GP_ + 255)/256, 256>>>(f0, f1, f2);
    topc_kernel<<<B_*C_, 256>>>(f0, f1, f2);
    fb_kernel<<<B_*C_, 256, 93824>>>(f0, f1, f2);
    nms_kernel<<<B_*C_, 128>>>();
    final_kernel<<<B_, 512>>>(out);
}

// round 6
// speedup vs baseline: 9.1514x; 1.4449x over previous
#include <cuda_runtime.h>
#include <math.h>
#include <stdint.h>

#define B_ 16
#define C_ 80
#define N_ 22743
#define K_ 100
#define CELLS_ 7581
#define M_ (C_*K_)
#define CAP_ 2048
#define PADTOT_ 22752
#define GP_ 5688          // 3*(91+361+1444) 4-cell groups per image
#define NSAMP_ 8192
#define NCH_ 8            // class chunks in scan
#define CPC_ 10           // classes per chunk

__device__ float g_boxes[B_*N_*4];
__device__ float g_conf_p[B_*PADTOT_];
__device__ float g_pth[B_*PADTOT_];
__device__ float g_tau[B_];
__device__ int   g_ccnt[B_*C_];
__device__ int   g_clist[(size_t)B_*C_*CAP_];
__device__ int   g_fbf[B_*C_];
__device__ float g_top_s[B_*M_];
__device__ float g_top_b[B_*M_*4];
__device__ float g_cand[B_*M_];

__constant__ int c_gg[3]   = {361,1444,5776};
__constant__ int c_noff[3] = {0,1083,5415};
__constant__ int c_soff[9] = {0,364,728,1092,2536,3980,5424,11200,16976};

__device__ __forceinline__ float sigmoidf_(float x){ return 1.0f/(1.0f+expf(-x)); }

// ---------------- decode: boxes + conf (+ zero counters) ---------------------
__global__ void decode_kernel(const float* __restrict__ f0, const float* __restrict__ f1,
                              const float* __restrict__ f2, const float* __restrict__ anchors,
                              const float* __restrict__ imshape){
    int tid = blockIdx.x*blockDim.x + threadIdx.x;
    if (tid < B_*C_){ g_ccnt[tid]=0; g_fbf[tid]=0; }
    if (tid >= B_*CELLS_) return;
    int b = tid / CELLS_, cp = tid % CELLS_;
    const float* feat; int g,l,noff,coff;
    if (cp < 361)       { feat=f0; g=19; l=0; noff=0;    coff=0;    }
    else if (cp < 1805) { feat=f1; g=38; l=1; noff=1083; coff=361;  }
    else                { feat=f2; g=76; l=2; noff=5415; coff=1805; }
    int cell = cp - coff, gg = g*g;
    int gy = cell/g, gx = cell%g;

    float imh = imshape[0], imw = imshape[1];
    const float ih = 608.0f, iw = 608.0f;
    float r  = fminf(ih/imh, iw/imw);
    float nh = rintf(imh*r), nw = rintf(imw*r);
    float offy = (ih-nh)*0.5f/ih, offx = (iw-nw)*0.5f/iw;
    float scy = ih/nh, scx = iw/nw;

    #pragma unroll
    for (int a = 0; a < 3; a++){
        const float* base = feat + ((size_t)b*255 + a*85)*(size_t)gg + cell;
        float tx = base[0], ty = base[(size_t)gg], tw = base[2*(size_t)gg];
        float th = base[3*(size_t)gg], to = base[4*(size_t)gg];
        float conf = sigmoidf_(to);
        float bx = (sigmoidf_(tx) + (float)gx)/(float)g;
        float by = (sigmoidf_(ty) + (float)gy)/(float)g;
        int aidx = (2-l)*3 + a;
        float bw = expf(tw)*anchors[aidx*2+0]/ih;
        float bh = expf(th)*anchors[aidx*2+1]/iw;
        float y = (by-offy)*scy, x = (bx-offx)*scx;
        float hh = bh*scy, ww = bw*scx;
        int n = noff + cell*3 + a;
        float* ob = &g_boxes[((size_t)b*N_ + n)*4];
        ob[0] = (y - hh*0.5f)*imh;
        ob[1] = (x - ww*0.5f)*imw;
        ob[2] = (y + hh*0.5f)*imh;
        ob[3] = (x + ww*0.5f)*imw;
        g_conf_p[(size_t)b*PADTOT_ + c_soff[l*3+a] + cell] = conf;
    }
}

// ---------------- per-image tau via 8192 exact samples -----------------------
__global__ void sample_kernel(const float* __restrict__ f0, const float* __restrict__ f1,
                              const float* __restrict__ f2){
    __shared__ float ss[NSAMP_];
    __shared__ int red[17];
    int b = blockIdx.x, tid = threadIdx.x;
    const float* feats[3] = {f0,f1,f2};
    for (int j = tid; j < NSAMP_; j += 512){
        uint32_t n = ((uint32_t)j*2654435761u + 971u) % N_;
        uint32_t c = ((uint32_t)j*48271u + 17u) % C_;
        int l = (n >= 5415) ? 2 : ((n >= 1083) ? 1 : 0);
        int rel = (int)n - c_noff[l];
        int cell = rel/3, a = rel - cell*3;
        float p = feats[l][((size_t)(b*255 + a*85 + 5 + (int)c))*c_gg[l] + cell];
        float conf = g_conf_p[(size_t)b*PADTOT_ + c_soff[l*3+a] + cell];
        ss[j] = conf * sigmoidf_(p);
    }
    __syncthreads();
    uint32_t lo = 0, hi = 0x3F800000u;
    for (int it = 0; it < 26; it++){
        float mv = __uint_as_float((lo + hi) >> 1);
        int cnt = 0;
        for (int j = tid; j < NSAMP_; j += 512) cnt += (ss[j] >= mv);
        for (int d = 16; d; d >>= 1) cnt += __shfl_down_sync(0xFFFFFFFFu, cnt, d);
        if ((tid & 31) == 0) red[tid >> 5] = cnt;
        __syncthreads();
        if (tid == 0){ int t=0; for (int w=0; w<16; w++) t += red[w]; red[16]=t; }
        __syncthreads();
        if (red[16] >= 144) lo = (lo+hi)>>1; else hi = (lo+hi)>>1;
        __syncthreads();
    }
    if (tid == 0) g_tau[b] = __uint_as_float(lo);
}

// ---------------- per-anchor p-threshold -------------------------------------
__global__ void pth_kernel(){
    int gid = blockIdx.x*blockDim.x + threadIdx.x;
    if (gid >= B_*PADTOT_) return;
    int b = gid / PADTOT_, s = gid % PADTOT_;
    int seg = 8;
    #pragma unroll
    for (int x = 1; x < 9; x++) if (s < c_soff[x]) { seg = x-1; break; }
    int l = seg/3, cell = s - c_soff[seg];
    float v = 1e30f;
    if (cell < c_gg[l]){
        float conf = g_conf_p[gid], tau = g_tau[b];
        if (conf > tau) v = logf(tau/(conf - tau)) - 3e-3f;
    }
    g_pth[gid] = v;
}

// ---------------- big scan: compare-only stream, class-chunked ---------------
__global__ __launch_bounds__(256) void scan_kernel(const float* __restrict__ f0,
                                                   const float* __restrict__ f1,
                                                   const float* __restrict__ f2){
    int gid = blockIdx.x*blockDim.x + threadIdx.x;
    if (gid >= B_*GP_) return;
    int ch = blockIdx.y;                          // class chunk
    int b = gid / GP_, r = gid % GP_;
    int l, a, q;
    if (r < 273)       { l = 0; a = r/91;   q = r - a*91;   }
    else if (r < 1356) { int rr=r-273;  l = 1; a = rr/361;  q = rr - a*361;  }
    else               { int rr=r-1356; l = 2; a = rr/1444; q = rr - a*1444; }
    int cell = q*4, gg = c_gg[l], noff = c_noff[l];
    const float* f = (l==0) ? f0 : ((l==1) ? f1 : f2);

    float4 pth = *(const float4*)&g_pth[(size_t)b*PADTOT_ + c_soff[l*3+a] + cell];
    float minp = fminf(fminf(pth.x, pth.y), fminf(pth.z, pth.w));
    if (!(minp < 1e29f)) return;

    const float* base = f + ((size_t)(b*255 + a*85 + 5 + ch*CPC_))*gg + cell;
    int bc0 = b*C_ + ch*CPC_;

    if (l == 0){
        bool v1 = cell+1 < gg, v2 = cell+2 < gg, v3 = cell+3 < gg;
        #pragma unroll 2
        for (int c = 0; c < CPC_; c++){
            const float* pp = base + (size_t)c*gg;
            float p0 = pp[0];
            float p1 = v1 ? pp[1] : -1e30f;
            float p2 = v2 ? pp[2] : -1e30f;
            float p3 = v3 ? pp[3] : -1e30f;
            float m = fmaxf(fmaxf(p0, p1), fmaxf(p2, p3));
            if (m >= minp){
                int bc = bc0 + c;
                if (p0>=pth.x){ int o=atomicAdd(&g_ccnt[bc],1); if(o<CAP_) g_clist[(size_t)bc*CAP_+o]=noff+(cell+0)*3+a; }
                if (p1>=pth.y){ int o=atomicAdd(&g_ccnt[bc],1); if(o<CAP_) g_clist[(size_t)bc*CAP_+o]=noff+(cell+1)*3+a; }
                if (p2>=pth.z){ int o=atomicAdd(&g_ccnt[bc],1); if(o<CAP_) g_clist[(size_t)bc*CAP_+o]=noff+(cell+2)*3+a; }
                if (p3>=pth.w){ int o=atomicAdd(&g_ccnt[bc],1); if(o<CAP_) g_clist[(size_t)bc*CAP_+o]=noff+(cell+3)*3+a; }
            }
        }
    } else {
        #pragma unroll 2
        for (int c = 0; c < CPC_; c++){
            float4 p = *(const float4*)(base + (size_t)c*gg);
            float m = fmaxf(fmaxf(p.x, p.y), fmaxf(p.z, p.w));
            if (m >= minp){
                int bc = bc0 + c;
                if (p.x>=pth.x){ int o=atomicAdd(&g_ccnt[bc],1); if(o<CAP_) g_clist[(size_t)bc*CAP_+o]=noff+(cell+0)*3+a; }
                if (p.y>=pth.y){ int o=atomicAdd(&g_ccnt[bc],1); if(o<CAP_) g_clist[(size_t)bc*CAP_+o]=noff+(cell+1)*3+a; }
                if (p.z>=pth.z){ int o=atomicAdd(&g_ccnt[bc],1); if(o<CAP_) g_clist[(size_t)bc*CAP_+o]=noff+(cell+2)*3+a; }
                if (p.w>=pth.w){ int o=atomicAdd(&g_ccnt[bc],1); if(o<CAP_) g_clist[(size_t)bc*CAP_+o]=noff+(cell+3)*3+a; }
            }
        }
    }
}

// ---------------- per-(b,c) exact top-100 from candidates --------------------
__global__ __launch_bounds__(256) void topc_kernel(const float* __restrict__ f0,
                                                   const float* __restrict__ f1,
                                                   const float* __restrict__ f2){
    __shared__ unsigned long long su[CAP_];
    __shared__ int s_ge;
    int blk = blockIdx.x, tid = threadIdx.x;
    int b = blk / C_, c = blk % C_;
    int cnt = g_ccnt[blk];
    if (cnt > CAP_){ if (tid == 0) g_fbf[blk] = 1; return; }
    float tau = g_tau[b];
    const float* feats[3] = {f0,f1,f2};

    if (tid == 0) s_ge = 0;
    for (int j = tid; j < CAP_; j += 256) su[j] = 0ULL;
    __syncthreads();

    int ge = 0;
    for (int j = tid; j < cnt; j += 256){
        int n = g_clist[(size_t)blk*CAP_ + j];
        int l = (n >= 5415) ? 2 : ((n >= 1083) ? 1 : 0);
        int rel = n - c_noff[l];
        int cell = rel/3, a = rel - cell*3;
        float p = feats[l][((size_t)(b*255 + a*85 + 5 + c))*c_gg[l] + cell];
        float conf = g_conf_p[(size_t)b*PADTOT_ + c_soff[l*3+a] + cell];
        float s = conf * sigmoidf_(p);
        ge += (s >= tau);
        su[j] = (((unsigned long long)__float_as_uint(s)) << 32)
              | (unsigned long long)(0xFFFFFFFFu - (uint32_t)n);
    }
    for (int d = 16; d; d >>= 1) ge += __shfl_down_sync(0xFFFFFFFFu, ge, d);
    if ((tid & 31) == 0) atomicAdd(&s_ge, ge);
    __syncthreads();
    if (s_ge < K_){ if (tid == 0) g_fbf[blk] = 1; return; }

    int P = 128; while (P < cnt) P <<= 1;
    for (int kk = 2; kk <= P; kk <<= 1)
        for (int j = kk >> 1; j > 0; j >>= 1){
            for (int m = tid; m < P; m += 256){
                int ixj = m ^ j;
                if (ixj > m){
                    unsigned long long A = su[m], Bv = su[ixj];
                    bool up = ((m & kk) == 0);
                    if (up ? (A < Bv) : (A > Bv)){ su[m] = Bv; su[ixj] = A; }
                }
            }
            __syncthreads();
        }
    if (tid < K_){
        unsigned long long sv = su[tid];
        int n = (int)(0xFFFFFFFFu - (uint32_t)sv);
        g_top_s[(size_t)blk*K_ + tid] = __uint_as_float((uint32_t)(sv >> 32));
        const float* bx = &g_boxes[((size_t)b*N_ + n)*4];
        float* ob = &g_top_b[((size_t)blk*K_ + tid)*4];
        ob[0]=bx[0]; ob[1]=bx[1]; ob[2]=bx[2]; ob[3]=bx[3];
    }
}

// ---------------- exact fallback for flagged blocks (rare) -------------------
__global__ __launch_bounds__(256) void fb_kernel(const float* __restrict__ f0,
                                                 const float* __restrict__ f1,
                                                 const float* __restrict__ f2){
    extern __shared__ char fsm[];
    float* q = (float*)fsm;
    uint32_t* bmp = (uint32_t*)(fsm + 90976);
    __shared__ unsigned long long wmax[8];
    int blk = blockIdx.x, tid = threadIdx.x;
    if (!g_fbf[blk]) return;
    int b = blk / C_, c = blk % C_;
    const float* feats[3] = {f0,f1,f2};
    for (int l = 0; l < 3; l++){
        int gg = c_gg[l], noff = c_noff[l];
        for (int a = 0; a < 3; a++){
            const float* pp  = feats[l] + ((size_t)(b*255 + a*85 + 5 + c))*gg;
            const float* cfp = g_conf_p + (size_t)b*PADTOT_ + c_soff[l*3+a];
            for (int i = tid; i < gg; i += 256)
                q[noff + i*3 + a] = cfp[i] * sigmoidf_(pp[i]);
        }
    }
    for (int i = tid; i < 712; i += 256) bmp[i] = 0;
    __syncthreads();
    for (int rr = 0; rr < K_; rr++){
        unsigned long long best = 0ULL;
        for (int i = tid; i < N_; i += 256){
            if (!((bmp[i>>5] >> (i & 31)) & 1u)){
                unsigned long long kk = (((unsigned long long)__float_as_uint(q[i])) << 32)
                                      | (unsigned long long)(0xFFFFFFFFu - (uint32_t)i);
                best = (kk > best) ? kk : best;
            }
        }
        for (int d = 16; d; d >>= 1){
            unsigned long long o = __shfl_down_sync(0xFFFFFFFFu, best, d);
            best = (o > best) ? o : best;
        }
        if ((tid & 31) == 0) wmax[tid >> 5] = best;
        __syncthreads();
        if (tid == 0){
            unsigned long long bb = 0ULL;
            for (int x = 0; x < 8; x++) bb = (wmax[x] > bb) ? wmax[x] : bb;
            int n = (int)(0xFFFFFFFFu - (uint32_t)bb);
            bmp[n>>5] |= (1u << (n & 31));
            g_top_s[(size_t)blk*K_ + rr] = __uint_as_float((uint32_t)(bb >> 32));
            const float* bx = &g_boxes[((size_t)b*N_ + n)*4];
            float* ob = &g_top_b[((size_t)blk*K_ + rr)*4];
            ob[0]=bx[0]; ob[1]=bx[1]; ob[2]=bx[2]; ob[3]=bx[3];
        }
        __syncthreads();
    }
}

// ---------------- greedy NMS per (b,c) ---------------------------------------
__global__ void nms_kernel(){
    __shared__ float y1s[K_], x1s[K_], y2s[K_], x2s[K_], ars[K_], scs[K_];
    __shared__ unsigned char vld[K_], sup[K_];
    int blk = blockIdx.x, tid = threadIdx.x;
    if (tid < K_){
        const float* bx = &g_top_b[((size_t)blk*K_ + tid)*4];
        float a0=bx[0], a1=bx[1], a2=bx[2], a3=bx[3];
        y1s[tid]=a0; x1s[tid]=a1; y2s[tid]=a2; x2s[tid]=a3;
        ars[tid] = fmaxf(a2-a0, 0.f)*fmaxf(a3-a1, 0.f);
        float s = g_top_s[(size_t)blk*K_ + tid];
        scs[tid]=s; vld[tid]=(s >= 0.2f); sup[tid]=0;
    }
    __syncthreads();
    for (int i = 0; i < K_; i++){
        bool keep_i = vld[i] && !sup[i];
        if (keep_i && tid > i && tid < K_){
            float iy1=fmaxf(y1s[i],y1s[tid]), ix1=fmaxf(x1s[i],x1s[tid]);
            float iy2=fminf(y2s[i],y2s[tid]), ix2=fminf(x2s[i],x2s[tid]);
            float inter=fmaxf(iy2-iy1,0.f)*fmaxf(ix2-ix1,0.f);
            if (inter/(ars[i]+ars[tid]-inter+1e-9f) > 0.3f) sup[tid]=1;
        }
        __syncthreads();
    }
    if (tid < K_)
        g_cand[(size_t)blk*K_ + tid] = (vld[tid] && !sup[tid]) ? scs[tid] : -1.0f;
}

// ---------------- final per-image top-100: u64 binary search -----------------
__global__ __launch_bounds__(512) void final_kernel(float* __restrict__ out){
    __shared__ int red;
    __shared__ unsigned long long list[128];
    __shared__ int pos;
    int b = blockIdx.x, tid = threadIdx.x;
    unsigned long long key[16];
    #pragma unroll
    for (int j = 0; j < 16; j++){
        int i = tid + j*512;
        unsigned long long kk = 0ULL;
        if (i < M_){
            uint32_t u = __float_as_uint(g_cand[(size_t)b*M_ + i]);
            uint32_t m = (u & 0x80000000u) ? ~u : (u | 0x80000000u);
            kk = (((unsigned long long)m) << 32) | (unsigned long long)(0xFFFFFFFFu - (uint32_t)i);
        }
        key[j] = kk;
    }
    unsigned long long lo = 0ULL, hi = 0xFFFFFFFFFFFFFFFFULL;
    for (int it = 0; it < 64 && hi - lo > 1ULL; it++){
        unsigned long long mid = lo + ((hi - lo) >> 1);
        if (tid == 0) red = 0;
        __syncthreads();
        int c = 0;
        #pragma unroll
        for (int j = 0; j < 16; j++) c += (key[j] >= mid);
        for (int d = 16; d; d >>= 1) c += __shfl_down_sync(0xFFFFFFFFu, c, d);
        if ((tid & 31) == 0) atomicAdd(&red, c);
        __syncthreads();
        if (red >= K_) lo = mid; else hi = mid;
        __syncthreads();
    }
    if (tid == 0) pos = 0;
    if (tid < 128) list[tid] = 0ULL;
    __syncthreads();
    #pragma unroll
    for (int j = 0; j < 16; j++)
        if (key[j] >= lo){ int p = atomicAdd(&pos, 1); if (p < 128) list[p] = key[j]; }
    __syncthreads();
    for (int k = 2; k <= 128; k <<= 1)
        for (int j = k >> 1; j > 0; j >>= 1){
            if (tid < 128){
                int ixj = tid ^ j;
                if (ixj > tid){
                    unsigned long long A = list[tid], Bv = list[ixj];
                    bool up = ((tid & k) == 0);
                    if (up ? (A < Bv) : (A > Bv)){ list[tid] = Bv; list[ixj] = A; }
                }
            }
            __syncthreads();
        }
    if (tid < K_){
        unsigned long long sv = list[tid];
        int idx = (int)(0xFFFFFFFFu - (uint32_t)sv);
        uint32_t m = (uint32_t)(sv >> 32);
        uint32_t ub = (m & 0x80000000u) ? (m & 0x7FFFFFFFu) : ~m;
        const float* bx = &g_top_b[((size_t)b*M_ + idx)*4];
        float* o = out + ((size_t)b*K_ + tid)*6;
        o[0]=bx[0]; o[1]=bx[1]; o[2]=bx[2]; o[3]=bx[3];
        o[4] = __uint_as_float(ub);
        o[5] = (float)(idx / K_);
    }
}

extern "C" void kernel_launch(void* const* d_in, const int* in_sizes, int n_in,
                              void* d_out, int out_size){
    const float* f0      = (const float*)d_in[0];
    const float* f1      = (const float*)d_in[1];
    const float* f2      = (const float*)d_in[2];
    const float* anchors = (const float*)d_in[3];
    const float* imshape = (const float*)d_in[4];
    float* out = (float*)d_out;

    cudaFuncSetAttribute(fb_kernel, cudaFuncAttributeMaxDynamicSharedMemorySize, 93824);

    decode_kernel<<<(B_*CELLS_ + 255)/256, 256>>>(f0, f1, f2, anchors, imshape);
    sample_kernel<<<B_, 512>>>(f0, f1, f2);
    pth_kernel<<<(B_*PADTOT_ + 255)/256, 256>>>();
    dim3 sg((B_*GP_ + 255)/256, NCH_);
    scan_kernel<<<sg, 256>>>(f0, f1, f2);
    topc_kernel<<<B_*C_, 256>>>(f0, f1, f2);
    fb_kernel<<<B_*C_, 256, 93824>>>(f0, f1, f2);
    nms_kernel<<<B_*C_, 128>>>();
    final_kernel<<<B_, 512>>>(out);
}